// round 3
// baseline (speedup 1.0000x reference)
#include <cuda_runtime.h>
#include <cstdint>

// Problem shape (fixed by the dataset):
//   x, y : (4, 4096, 512) float32
//   filt : (128,)         float32
//   out  : (4, 4096, 4096) float32
#define BATCH 4
#define NROWS 4096
#define DIM   512
#define RANK  128
#define FEAT  256   // 2*RANK (re/im interleaved)

#define MTOT (BATCH * NROWS)   // 16384 rows per tensor

// Scratch (device globals: no allocation allowed in kernel_launch)
__device__ float g_basis[DIM * FEAT];        // 512 KB
__device__ float g_fx[BATCH * NROWS * FEAT]; // 16 MB
__device__ float g_fy[BATCH * NROWS * FEAT]; // 16 MB

// ---------------------------------------------------------------------------
// packed f32x2 helpers (sm_103a): 2 fp32 FMA results per fma-pipe issue
// ---------------------------------------------------------------------------
__device__ __forceinline__ unsigned long long pack2(float v) {
    unsigned long long r;
    asm("mov.b64 %0, {%1, %1};" : "=l"(r) : "f"(v));
    return r;
}

#define FMA_F32X2(acc, a, b) \
    asm("fma.rn.f32x2 %0, %1, %2, %0;" : "+l"(acc) : "l"(a), "l"(b))

// ---------------------------------------------------------------------------
// Kernel 1: build spectral basis
//   g_basis[k][2r]   =  cos(2*pi*k*r/512) * filt[r]
//   g_basis[k][2r+1] = -sin(2*pi*k*r/512) * filt[r]
// Angle reduced exactly with integer mod before sincosf.
// ---------------------------------------------------------------------------
__global__ void build_basis(const float* __restrict__ filt) {
    int idx = blockIdx.x * blockDim.x + threadIdx.x; // 0 .. 512*256-1
    int k = idx >> 8;
    int c = idx & 255;
    int r = c >> 1;
    int phase = (k * r) & (DIM - 1);
    float ang = (float)phase * (6.283185307179586f / (float)DIM);
    float s, co;
    sincosf(ang, &s, &co);
    float f = filt[r];
    g_basis[idx] = ((c & 1) ? -s : co) * f;
}

// ---------------------------------------------------------------------------
// Kernel 2: feature GEMM (NN):  F = X @ C,  (16384 x 512) @ (512 x 256)
// Tile 128(m) x 64(n) x 16(k), 256 threads, 8x4 microtile, plain fp32.
// Software-pipelined: next k-tile prefetched into registers during compute.
// blockIdx.z selects x->g_fx vs y->g_fy.
// ---------------------------------------------------------------------------
__global__ __launch_bounds__(256) void feat_gemm(const float* __restrict__ x,
                                                 const float* __restrict__ y) {
    const float* __restrict__ src = blockIdx.z ? y : x;
    float* __restrict__ dst = blockIdx.z ? g_fy : g_fx;

    __shared__ float As[16][128]; // [k][m] (transposed on store)
    __shared__ float Bs[16][64];  // [k][n]

    const int m0 = blockIdx.x * 128;
    const int n0 = blockIdx.y * 64;
    const int tid = threadIdx.x;
    const int tx = tid & 15;   // n-group: 16 * 4 = 64
    const int ty = tid >> 4;   // m-group: 16 * 8 = 128

    // Per-thread load coordinates (A: 2 float4, B: 1 float4)
    const int a_row0 = tid >> 2;
    const int a_c4   = (tid & 3) * 4;
    const int b_row  = tid >> 4;
    const int b_c4   = (tid & 15) * 4;

    float acc[8][4];
#pragma unroll
    for (int i = 0; i < 8; i++)
#pragma unroll
        for (int j = 0; j < 4; j++) acc[i][j] = 0.0f;

    // Prologue: fetch k-tile 0
    float4 pa0 = *(const float4*)&src[(size_t)(m0 + a_row0) * DIM + a_c4];
    float4 pa1 = *(const float4*)&src[(size_t)(m0 + a_row0 + 64) * DIM + a_c4];
    float4 pb  = *(const float4*)&g_basis[(size_t)b_row * FEAT + n0 + b_c4];

    for (int k0 = 0; k0 < DIM; k0 += 16) {
        // Commit current tile to smem
        As[a_c4 + 0][a_row0] = pa0.x;
        As[a_c4 + 1][a_row0] = pa0.y;
        As[a_c4 + 2][a_row0] = pa0.z;
        As[a_c4 + 3][a_row0] = pa0.w;
        As[a_c4 + 0][a_row0 + 64] = pa1.x;
        As[a_c4 + 1][a_row0 + 64] = pa1.y;
        As[a_c4 + 2][a_row0 + 64] = pa1.z;
        As[a_c4 + 3][a_row0 + 64] = pa1.w;
        *(float4*)&Bs[b_row][b_c4] = pb;
        __syncthreads();

        // Prefetch next tile (registers) while computing this one
        int kn = k0 + 16;
        if (kn < DIM) {
            pa0 = *(const float4*)&src[(size_t)(m0 + a_row0) * DIM + kn + a_c4];
            pa1 = *(const float4*)&src[(size_t)(m0 + a_row0 + 64) * DIM + kn + a_c4];
            pb  = *(const float4*)&g_basis[(size_t)(kn + b_row) * FEAT + n0 + b_c4];
        }

#pragma unroll
        for (int kk = 0; kk < 16; kk++) {
            float4 a0 = *(const float4*)&As[kk][ty * 8];
            float4 a1 = *(const float4*)&As[kk][ty * 8 + 4];
            float4 b  = *(const float4*)&Bs[kk][tx * 4];
            float a[8] = {a0.x, a0.y, a0.z, a0.w, a1.x, a1.y, a1.z, a1.w};
            float bb[4] = {b.x, b.y, b.z, b.w};
#pragma unroll
            for (int i = 0; i < 8; i++)
#pragma unroll
                for (int j = 0; j < 4; j++) acc[i][j] = fmaf(a[i], bb[j], acc[i][j]);
        }
        __syncthreads();
    }

#pragma unroll
    for (int i = 0; i < 8; i++) {
        float4 v = make_float4(acc[i][0], acc[i][1], acc[i][2], acc[i][3]);
        *(float4*)&dst[(size_t)(m0 + ty * 8 + i) * FEAT + n0 + tx * 4] = v;
    }
}

// ---------------------------------------------------------------------------
// Kernel 3: batched Gram GEMM (NT):
//   out[b,n,m] = dot(Fx[b,n,:], Fy[b,m,:]) / 128
// Tile 128x128x16, 256 threads, 8x8 microtile via packed f32x2 FMA
// (8 broadcast-packed A values x 4 packed B pairs -> 32 FMA2 = 64 FMA / k).
// Double-buffered smem (ping-pong): ONE barrier per k-tile; global->register
// prefetch and smem commit of tile t+1 overlap the FMA block of tile t.
// ---------------------------------------------------------------------------
__global__ __launch_bounds__(256) void gram_gemm(float* __restrict__ out) {
    const int b  = blockIdx.z;
    const int n0 = blockIdx.y * 128;  // x-row tile
    const int m0 = blockIdx.x * 128;  // y-row tile

    const float* __restrict__ A  = g_fx + (size_t)b * NROWS * FEAT;
    const float* __restrict__ Bm = g_fy + (size_t)b * NROWS * FEAT;

    // Double-buffered tiles: [buf][k][row], +4 pad kills transpose conflicts
    __shared__ float As[2][16][132];
    __shared__ float Bs[2][16][132];

    const int tid = threadIdx.x;
    const int tx = tid & 15;   // m-group: 16 * 8 = 128
    const int ty = tid >> 4;   // n-group: 16 * 8 = 128

    // Per-thread load coords: each thread loads 2 float4 from A, 2 from B
    const int l_row0 = tid >> 2;        // 0..63
    const int l_c4   = (tid & 3) * 4;   // 0,4,8,12

    unsigned long long acc[8][4];
#pragma unroll
    for (int i = 0; i < 8; i++)
#pragma unroll
        for (int j = 0; j < 4; j++) acc[i][j] = 0ULL;

    // --- Prologue: load k-tile 0 and commit into buffer 0 ---
    {
        float4 va0 = *(const float4*)&A [(size_t)(n0 + l_row0)      * FEAT + l_c4];
        float4 va1 = *(const float4*)&A [(size_t)(n0 + l_row0 + 64) * FEAT + l_c4];
        float4 vb0 = *(const float4*)&Bm[(size_t)(m0 + l_row0)      * FEAT + l_c4];
        float4 vb1 = *(const float4*)&Bm[(size_t)(m0 + l_row0 + 64) * FEAT + l_c4];
        As[0][l_c4 + 0][l_row0] = va0.x;
        As[0][l_c4 + 1][l_row0] = va0.y;
        As[0][l_c4 + 2][l_row0] = va0.z;
        As[0][l_c4 + 3][l_row0] = va0.w;
        As[0][l_c4 + 0][l_row0 + 64] = va1.x;
        As[0][l_c4 + 1][l_row0 + 64] = va1.y;
        As[0][l_c4 + 2][l_row0 + 64] = va1.z;
        As[0][l_c4 + 3][l_row0 + 64] = va1.w;
        Bs[0][l_c4 + 0][l_row0] = vb0.x;
        Bs[0][l_c4 + 1][l_row0] = vb0.y;
        Bs[0][l_c4 + 2][l_row0] = vb0.z;
        Bs[0][l_c4 + 3][l_row0] = vb0.w;
        Bs[0][l_c4 + 0][l_row0 + 64] = vb1.x;
        Bs[0][l_c4 + 1][l_row0 + 64] = vb1.y;
        Bs[0][l_c4 + 2][l_row0 + 64] = vb1.z;
        Bs[0][l_c4 + 3][l_row0 + 64] = vb1.w;
    }
    __syncthreads();

    int buf = 0;
    for (int k0 = 0; k0 < FEAT; k0 += 16) {
        const int kn = k0 + 16;
        const int nbuf = buf ^ 1;

        // Prefetch next k-tile from global (issues early; consumed mid-loop)
        float4 va0, va1, vb0, vb1;
        if (kn < FEAT) {
            va0 = *(const float4*)&A [(size_t)(n0 + l_row0)      * FEAT + kn + l_c4];
            va1 = *(const float4*)&A [(size_t)(n0 + l_row0 + 64) * FEAT + kn + l_c4];
            vb0 = *(const float4*)&Bm[(size_t)(m0 + l_row0)      * FEAT + kn + l_c4];
            vb1 = *(const float4*)&Bm[(size_t)(m0 + l_row0 + 64) * FEAT + kn + l_c4];
        }

        // FMA block on current buffer, with next-tile smem commit interleaved
        // after the first half of the k-steps (loads have landed by then).
#pragma unroll
        for (int kk = 0; kk < 16; kk++) {
            if (kk == 8 && kn < FEAT) {
                // Commit next tile into the other buffer (no barrier needed:
                // nobody reads nbuf until the barrier below).
                As[nbuf][l_c4 + 0][l_row0] = va0.x;
                As[nbuf][l_c4 + 1][l_row0] = va0.y;
                As[nbuf][l_c4 + 2][l_row0] = va0.z;
                As[nbuf][l_c4 + 3][l_row0] = va0.w;
                As[nbuf][l_c4 + 0][l_row0 + 64] = va1.x;
                As[nbuf][l_c4 + 1][l_row0 + 64] = va1.y;
                As[nbuf][l_c4 + 2][l_row0 + 64] = va1.z;
                As[nbuf][l_c4 + 3][l_row0 + 64] = va1.w;
                Bs[nbuf][l_c4 + 0][l_row0] = vb0.x;
                Bs[nbuf][l_c4 + 1][l_row0] = vb0.y;
                Bs[nbuf][l_c4 + 2][l_row0] = vb0.z;
                Bs[nbuf][l_c4 + 3][l_row0] = vb0.w;
                Bs[nbuf][l_c4 + 0][l_row0 + 64] = vb1.x;
                Bs[nbuf][l_c4 + 1][l_row0 + 64] = vb1.y;
                Bs[nbuf][l_c4 + 2][l_row0 + 64] = vb1.z;
                Bs[nbuf][l_c4 + 3][l_row0 + 64] = vb1.w;
            }
            float4 a0 = *(const float4*)&As[buf][kk][ty * 8];
            float4 a1 = *(const float4*)&As[buf][kk][ty * 8 + 4];
            ulonglong2 bp0 = *(const ulonglong2*)&Bs[buf][kk][tx * 8];
            ulonglong2 bp1 = *(const ulonglong2*)&Bs[buf][kk][tx * 8 + 4];
            unsigned long long a2[8];
            a2[0] = pack2(a0.x); a2[1] = pack2(a0.y);
            a2[2] = pack2(a0.z); a2[3] = pack2(a0.w);
            a2[4] = pack2(a1.x); a2[5] = pack2(a1.y);
            a2[6] = pack2(a1.z); a2[7] = pack2(a1.w);
            unsigned long long bb[4] = {bp0.x, bp0.y, bp1.x, bp1.y};
#pragma unroll
            for (int i = 0; i < 8; i++) {
#pragma unroll
                for (int j = 0; j < 4; j++) {
                    FMA_F32X2(acc[i][j], a2[i], bb[j]);
                }
            }
        }
        // Single barrier per iteration: ensures everyone finished reading buf
        // AND the nbuf commit is visible before the swap.
        __syncthreads();
        buf = nbuf;
    }

    // Epilogue: unpack, scale by 1/128, vectorized store
    const float scale = 1.0f / (float)RANK;
#pragma unroll
    for (int i = 0; i < 8; i++) {
        float v[8];
#pragma unroll
        for (int j = 0; j < 4; j++) {
            unsigned long long u = acc[i][j];
            v[2 * j]     = __uint_as_float((unsigned)(u & 0xFFFFFFFFu)) * scale;
            v[2 * j + 1] = __uint_as_float((unsigned)(u >> 32)) * scale;
        }
        size_t row = (size_t)b * NROWS + (n0 + ty * 8 + i);
        float4* p = (float4*)&out[row * NROWS + m0 + tx * 8];
        p[0] = make_float4(v[0], v[1], v[2], v[3]);
        p[1] = make_float4(v[4], v[5], v[6], v[7]);
    }
}

// ---------------------------------------------------------------------------
extern "C" void kernel_launch(void* const* d_in, const int* in_sizes, int n_in,
                              void* d_out, int out_size) {
    const float* x    = (const float*)d_in[0];
    const float* y    = (const float*)d_in[1];
    const float* filt = (const float*)d_in[2];
    float* out = (float*)d_out;

    // 1) spectral basis (512 x 256)
    build_basis<<<DIM * FEAT / 256, 256>>>(filt);

    // 2) features: (16384 x 512) @ (512 x 256) for x and y (grid.z)
    dim3 fgrid(MTOT / 128, FEAT / 64, 2);
    feat_gemm<<<fgrid, 256>>>(x, y);

    // 3) batched Gram: out[b] = Fx[b] @ Fy[b]^T / 128
    dim3 ggrid(NROWS / 128, NROWS / 128, BATCH);
    gram_gemm<<<ggrid, 256>>>(out);
}

// round 11
// speedup vs baseline: 1.8891x; 1.8891x over previous
#include <cuda_runtime.h>
#include <cuda_bf16.h>
#include <cstdint>

// Problem shape (fixed by the dataset):
//   x, y : (4, 4096, 512) float32
//   filt : (128,)         float32
//   out  : (4, 4096, 4096) float32
#define BATCH 4
#define NROWS 4096
#define DIM   512
#define RANK  128
#define FEAT  256    // 2*RANK (re/im interleaved)
// Split-bf16 feature encoding with cross terms:
//   x rows: [hx(256) | lx(256) | hx(256)]
//   y rows: [hy(256) | hy(256) | ly(256)]
//   dot_768 = hx.hy + lx.hy + hx.ly   (only lx.ly dropped, ~2^-18 rel)
#define FEAT3 768
#define MTOT  (BATCH * NROWS)

// Scratch (device globals: no allocation allowed in kernel_launch)
__device__ float g_basis[DIM * FEAT];                  // 512 KB
__device__ __nv_bfloat16 g_fx[MTOT * FEAT3];           // 24 MB
__device__ __nv_bfloat16 g_fy[MTOT * FEAT3];           // 24 MB

// ---------------------------------------------------------------------------
// helpers
// ---------------------------------------------------------------------------
__device__ __forceinline__ unsigned long long pack2(float v) {
    unsigned long long r;
    asm("mov.b64 %0, {%1, %1};" : "=l"(r) : "f"(v));
    return r;
}
#define FMA_F32X2(acc, a, b) \
    asm("fma.rn.f32x2 %0, %1, %2, %0;" : "+l"(acc) : "l"(a), "l"(b))

__device__ __forceinline__ uint32_t smem_to_u32(const void* p) {
    uint32_t a;
    asm("{ .reg .u64 t; cvta.to.shared.u64 t, %1; cvt.u32.u64 %0, t; }"
        : "=r"(a) : "l"(p));
    return a;
}

__device__ __forceinline__ void ldsm4(uint32_t addr, uint32_t* r) {
    asm volatile("ldmatrix.sync.aligned.m8n8.x4.shared.b16 {%0,%1,%2,%3}, [%4];"
                 : "=r"(r[0]), "=r"(r[1]), "=r"(r[2]), "=r"(r[3]) : "r"(addr));
}

__device__ __forceinline__ void mma16816(float* c, const uint32_t* a,
                                         uint32_t b0, uint32_t b1) {
    asm volatile(
        "mma.sync.aligned.m16n8k16.row.col.f32.bf16.bf16.f32 "
        "{%0,%1,%2,%3}, {%4,%5,%6,%7}, {%8,%9}, {%0,%1,%2,%3};"
        : "+f"(c[0]), "+f"(c[1]), "+f"(c[2]), "+f"(c[3])
        : "r"(a[0]), "r"(a[1]), "r"(a[2]), "r"(a[3]), "r"(b0), "r"(b1));
}

// ---------------------------------------------------------------------------
// Kernel 1: build spectral basis (fp32)
//   g_basis[k][2r]   =  cos(2*pi*k*r/512) * filt[r]
//   g_basis[k][2r+1] = -sin(2*pi*k*r/512) * filt[r]
// ---------------------------------------------------------------------------
__global__ void build_basis(const float* __restrict__ filt) {
    int idx = blockIdx.x * blockDim.x + threadIdx.x; // 0 .. 512*256-1
    int k = idx >> 8;
    int c = idx & 255;
    int r = c >> 1;
    int phase = (k * r) & (DIM - 1);
    float ang = (float)phase * (6.283185307179586f / (float)DIM);
    float s, co;
    sincosf(ang, &s, &co);
    float f = filt[r];
    g_basis[idx] = ((c & 1) ? -s : co) * f;
}

// ---------------------------------------------------------------------------
// Kernel 2: feature GEMM (NN):  F = X @ C, (16384 x 512) @ (512 x 256), fp32
// f32x2 accumulators; epilogue splits each feature into bf16 hi + lo and
// stores 3 segments:  x -> [hi | lo | hi],  y -> [hi | hi | lo].
// ---------------------------------------------------------------------------
__global__ __launch_bounds__(256) void feat_gemm(const float* __restrict__ x,
                                                 const float* __restrict__ y) {
    const int isY = blockIdx.z;
    const float* __restrict__ src = isY ? y : x;
    __nv_bfloat16* __restrict__ dst = isY ? g_fy : g_fx;

    __shared__ float As[16][128]; // [k][m]
    __shared__ float Bs[16][64];  // [k][n]

    const int m0 = blockIdx.x * 128;
    const int n0 = blockIdx.y * 64;
    const int tid = threadIdx.x;
    const int tx = tid & 15;   // n-group: 16 * 4 = 64
    const int ty = tid >> 4;   // m-group: 16 * 8 = 128

    const int a_row0 = tid >> 2;
    const int a_c4   = (tid & 3) * 4;
    const int b_row  = tid >> 4;
    const int b_c4   = (tid & 15) * 4;

    unsigned long long acc[8][2];
#pragma unroll
    for (int i = 0; i < 8; i++) { acc[i][0] = 0ULL; acc[i][1] = 0ULL; }

    float4 pa0 = *(const float4*)&src[(size_t)(m0 + a_row0) * DIM + a_c4];
    float4 pa1 = *(const float4*)&src[(size_t)(m0 + a_row0 + 64) * DIM + a_c4];
    float4 pb  = *(const float4*)&g_basis[(size_t)b_row * FEAT + n0 + b_c4];

    for (int k0 = 0; k0 < DIM; k0 += 16) {
        As[a_c4 + 0][a_row0] = pa0.x;
        As[a_c4 + 1][a_row0] = pa0.y;
        As[a_c4 + 2][a_row0] = pa0.z;
        As[a_c4 + 3][a_row0] = pa0.w;
        As[a_c4 + 0][a_row0 + 64] = pa1.x;
        As[a_c4 + 1][a_row0 + 64] = pa1.y;
        As[a_c4 + 2][a_row0 + 64] = pa1.z;
        As[a_c4 + 3][a_row0 + 64] = pa1.w;
        *(float4*)&Bs[b_row][b_c4] = pb;
        __syncthreads();

        int kn = k0 + 16;
        if (kn < DIM) {
            pa0 = *(const float4*)&src[(size_t)(m0 + a_row0) * DIM + kn + a_c4];
            pa1 = *(const float4*)&src[(size_t)(m0 + a_row0 + 64) * DIM + kn + a_c4];
            pb  = *(const float4*)&g_basis[(size_t)(kn + b_row) * FEAT + n0 + b_c4];
        }

#pragma unroll
        for (int kk = 0; kk < 16; kk++) {
            float4 a0 = *(const float4*)&As[kk][ty * 8];
            float4 a1 = *(const float4*)&As[kk][ty * 8 + 4];
            ulonglong2 bp = *(const ulonglong2*)&Bs[kk][tx * 4];
            float a[8] = {a0.x, a0.y, a0.z, a0.w, a1.x, a1.y, a1.z, a1.w};
#pragma unroll
            for (int i = 0; i < 8; i++) {
                unsigned long long a2 = pack2(a[i]);
                FMA_F32X2(acc[i][0], a2, bp.x);
                FMA_F32X2(acc[i][1], a2, bp.y);
            }
        }
        __syncthreads();
    }

    // Epilogue: split into bf16 hi + lo, store 3 segments.
    //   x rows: seg0 = hi, seg1 = lo, seg2 = hi
    //   y rows: seg0 = hi, seg1 = hi, seg2 = lo
#pragma unroll
    for (int i = 0; i < 8; i++) {
        float v[4];
#pragma unroll
        for (int j = 0; j < 2; j++) {
            unsigned long long u = acc[i][j];
            v[2 * j]     = __uint_as_float((unsigned)(u & 0xFFFFFFFFu));
            v[2 * j + 1] = __uint_as_float((unsigned)(u >> 32));
        }
        union { __nv_bfloat16 h[4]; uint2 u; } hv;
        union { __nv_bfloat16 h[4]; uint2 u; } lv;
#pragma unroll
        for (int j = 0; j < 4; j++) {
            __nv_bfloat16 h = __float2bfloat16(v[j]);
            hv.h[j] = h;
            lv.h[j] = __float2bfloat16(v[j] - __bfloat162float(h));
        }
        size_t base = (size_t)(m0 + ty * 8 + i) * FEAT3 + n0 + tx * 4;
        *(uint2*)&dst[base]            = hv.u;                  // seg0: hi
        *(uint2*)&dst[base + FEAT]     = isY ? hv.u : lv.u;     // seg1
        *(uint2*)&dst[base + 2 * FEAT] = isY ? lv.u : hv.u;     // seg2
    }
}

// ---------------------------------------------------------------------------
// Kernel 3: batched Gram GEMM via mma.sync (bf16, fp32 accum), K = 768
//   out[b,i,j] = dot(fx[b,i,0:768], fy[b,j,0:768]) / 128
//              = (hx.hy + lx.hy + hx.ly) / 128      (lx.ly dropped, ~2^-18)
// CTA tile 128(i) x 128(j); 8 warps = 4(i) x 2(j); warp tile 32(i) x 64(j);
// kc=32 double-buffered smem, pad to 40 bf16/row (80B: conflict-free ldmatrix).
// ---------------------------------------------------------------------------
#define KC   32
#define LDSM 40   // padded row length in bf16

__global__ __launch_bounds__(256, 2) void gram_mma(float* __restrict__ out) {
    __shared__ __nv_bfloat16 As[2][128 * LDSM]; // Fx tile (i rows)
    __shared__ __nv_bfloat16 Bs[2][128 * LDSM]; // Fy tile (j rows)

    const int tid  = threadIdx.x;
    const int wid  = tid >> 5;
    const int lane = tid & 31;

    const int b  = blockIdx.z;
    const int j0 = blockIdx.x * 128;  // Fy rows -> out last dim (contiguous)
    const int i0 = blockIdx.y * 128;  // Fx rows -> out middle dim

    const __nv_bfloat16* Ag = g_fx + (size_t)b * NROWS * FEAT3;
    const __nv_bfloat16* Bg = g_fy + (size_t)b * NROWS * FEAT3;

    const int i0w = (wid & 3) * 32;   // warp i-offset
    const int j0w = (wid >> 2) * 64;  // warp j-offset

    // global-load coords: 4 threads per row (4 x 16B = 64B = 32 bf16)
    const int rowL = tid >> 2;        // 0..63
    const int c16  = (tid & 3) * 8;   // bf16 offset: 0,8,16,24

    const uint32_t aSm = smem_to_u32(As);
    const uint32_t bSm = smem_to_u32(Bs);
    const uint32_t stageB = 128 * LDSM * 2; // bytes per stage

    float acc[2][8][4];
#pragma unroll
    for (int ti = 0; ti < 2; ti++)
#pragma unroll
        for (int tj = 0; tj < 8; tj++)
#pragma unroll
            for (int q = 0; q < 4; q++) acc[ti][tj][q] = 0.0f;

    // ---- prologue: stage 0 ----
    {
        uint4 ra0 = *(const uint4*)&Ag[(size_t)(i0 + rowL) * FEAT3 + c16];
        uint4 ra1 = *(const uint4*)&Ag[(size_t)(i0 + rowL + 64) * FEAT3 + c16];
        uint4 rb0 = *(const uint4*)&Bg[(size_t)(j0 + rowL) * FEAT3 + c16];
        uint4 rb1 = *(const uint4*)&Bg[(size_t)(j0 + rowL + 64) * FEAT3 + c16];
        *(uint4*)&As[0][rowL * LDSM + c16] = ra0;
        *(uint4*)&As[0][(rowL + 64) * LDSM + c16] = ra1;
        *(uint4*)&Bs[0][rowL * LDSM + c16] = rb0;
        *(uint4*)&Bs[0][(rowL + 64) * LDSM + c16] = rb1;
    }
    __syncthreads();

    int buf = 0;
    for (int s = 0; s < FEAT3 / KC; s++) {
        // prefetch next stage into registers
        uint4 ra0, ra1, rb0, rb1;
        const int kn = (s + 1) * KC;
        if (kn < FEAT3) {
            ra0 = *(const uint4*)&Ag[(size_t)(i0 + rowL) * FEAT3 + kn + c16];
            ra1 = *(const uint4*)&Ag[(size_t)(i0 + rowL + 64) * FEAT3 + kn + c16];
            rb0 = *(const uint4*)&Bg[(size_t)(j0 + rowL) * FEAT3 + kn + c16];
            rb1 = *(const uint4*)&Bg[(size_t)(j0 + rowL + 64) * FEAT3 + kn + c16];
        }

        // compute on current buffer: 2 k16 steps
        const uint32_t aBase = aSm + buf * stageB;
        const uint32_t bBase = bSm + buf * stageB;
#pragma unroll
        for (int ks = 0; ks < 2; ks++) {
            uint32_t af[2][4];
#pragma unroll
            for (int ti = 0; ti < 2; ti++) {
                int row = i0w + ti * 16 + (lane & 15);
                uint32_t off = (uint32_t)(row * LDSM + ks * 16 + ((lane >> 4) << 3)) * 2;
                ldsm4(aBase + off, af[ti]);
            }
#pragma unroll
            for (int tp = 0; tp < 4; tp++) {
                uint32_t bf[4];
                int row = j0w + tp * 16 + ((lane >> 4) << 3) + (lane & 7);
                uint32_t off = (uint32_t)(row * LDSM + ks * 16 + (((lane >> 3) & 1) << 3)) * 2;
                ldsm4(bBase + off, bf);
#pragma unroll
                for (int ti = 0; ti < 2; ti++) {
                    mma16816(acc[ti][tp * 2], af[ti], bf[0], bf[1]);
                    mma16816(acc[ti][tp * 2 + 1], af[ti], bf[2], bf[3]);
                }
            }
        }

        // commit next stage to the other buffer
        if (kn < FEAT3) {
            const int nb = buf ^ 1;
            *(uint4*)&As[nb][rowL * LDSM + c16] = ra0;
            *(uint4*)&As[nb][(rowL + 64) * LDSM + c16] = ra1;
            *(uint4*)&Bs[nb][rowL * LDSM + c16] = rb0;
            *(uint4*)&Bs[nb][(rowL + 64) * LDSM + c16] = rb1;
        }
        __syncthreads();
        buf ^= 1;
    }

    // ---- epilogue: scale by 1/128, float2 stores ----
    const float scale = 1.0f / (float)RANK;
#pragma unroll
    for (int ti = 0; ti < 2; ti++) {
#pragma unroll
        for (int tj = 0; tj < 8; tj++) {
            int i = i0 + i0w + ti * 16 + (lane >> 2);
            int j = j0 + j0w + tj * 8 + (lane & 3) * 2;
            size_t base = ((size_t)b * NROWS + i) * NROWS + j;
            float2 v0 = make_float2(acc[ti][tj][0] * scale, acc[ti][tj][1] * scale);
            float2 v1 = make_float2(acc[ti][tj][2] * scale, acc[ti][tj][3] * scale);
            *(float2*)&out[base] = v0;
            *(float2*)&out[base + (size_t)8 * NROWS] = v1;
        }
    }
}

// ---------------------------------------------------------------------------
extern "C" void kernel_launch(void* const* d_in, const int* in_sizes, int n_in,
                              void* d_out, int out_size) {
    const float* x    = (const float*)d_in[0];
    const float* y    = (const float*)d_in[1];
    const float* filt = (const float*)d_in[2];
    float* out = (float*)d_out;

    // 1) spectral basis (512 x 256)
    build_basis<<<DIM * FEAT / 256, 256>>>(filt);

    // 2) features + split-bf16: x -> [hi|lo|hi], y -> [hi|hi|lo]
    dim3 fgrid(MTOT / 128, FEAT / 64, 2);
    feat_gemm<<<fgrid, 256>>>(x, y);

    // 3) batched Gram on legacy tensor cores (mma.sync bf16, K=768)
    dim3 ggrid(NROWS / 128, NROWS / 128, BATCH);
    gram_mma<<<ggrid, 256>>>(out);
}

// round 12
// speedup vs baseline: 2.1195x; 1.1219x over previous
#include <cuda_runtime.h>
#include <cuda_bf16.h>
#include <cstdint>

// Problem shape (fixed by the dataset):
//   x, y : (4, 4096, 512) float32
//   filt : (128,)         float32
//   out  : (4, 4096, 4096) float32
#define BATCH 4
#define NROWS 4096
#define DIM   512
#define RANK  128
#define FEAT  256    // 2*RANK (re/im interleaved)
// Gram feature encoding (verified R11):
//   x rows: [hx(256) | lx(256) | hx(256)]
//   y rows: [hy(256) | hy(256) | ly(256)]
//   dot_768 = hx.hy + lx.hy + hx.ly   (only lx.ly dropped)
#define FEAT3 768
// Feature-GEMM input encoding (same trick on X and basis):
//   X rows:   [Xh(512) | Xl(512) | Xh(512)]
//   C^T rows: [Ch(512) | Ch(512) | Cl(512)]
#define FEATX 1536
#define MTOT  (BATCH * NROWS)

// Scratch (device globals: no allocation allowed in kernel_launch)
__device__ __nv_bfloat16 g_bsplit[FEAT * FEATX];       // 768 KB  C^T split
__device__ __nv_bfloat16 g_xs[MTOT * FEATX];           // 48 MB   X split
__device__ __nv_bfloat16 g_ys[MTOT * FEATX];           // 48 MB   Y split
__device__ __nv_bfloat16 g_fx[MTOT * FEAT3];           // 24 MB   features x
__device__ __nv_bfloat16 g_fy[MTOT * FEAT3];           // 24 MB   features y

// ---------------------------------------------------------------------------
// helpers
// ---------------------------------------------------------------------------
__device__ __forceinline__ uint32_t smem_to_u32(const void* p) {
    uint32_t a;
    asm("{ .reg .u64 t; cvta.to.shared.u64 t, %1; cvt.u32.u64 %0, t; }"
        : "=r"(a) : "l"(p));
    return a;
}

__device__ __forceinline__ void ldsm4(uint32_t addr, uint32_t* r) {
    asm volatile("ldmatrix.sync.aligned.m8n8.x4.shared.b16 {%0,%1,%2,%3}, [%4];"
                 : "=r"(r[0]), "=r"(r[1]), "=r"(r[2]), "=r"(r[3]) : "r"(addr));
}

__device__ __forceinline__ void mma16816(float* c, const uint32_t* a,
                                         uint32_t b0, uint32_t b1) {
    asm volatile(
        "mma.sync.aligned.m16n8k16.row.col.f32.bf16.bf16.f32 "
        "{%0,%1,%2,%3}, {%4,%5,%6,%7}, {%8,%9}, {%0,%1,%2,%3};"
        : "+f"(c[0]), "+f"(c[1]), "+f"(c[2]), "+f"(c[3])
        : "r"(a[0]), "r"(a[1]), "r"(a[2]), "r"(a[3]), "r"(b0), "r"(b1));
}

__device__ __forceinline__ uint32_t split_pair(float f0, float f1, uint32_t& lo_out) {
    __nv_bfloat16 h0 = __float2bfloat16(f0);
    __nv_bfloat16 h1 = __float2bfloat16(f1);
    __nv_bfloat16 l0 = __float2bfloat16(f0 - __bfloat162float(h0));
    __nv_bfloat16 l1 = __float2bfloat16(f1 - __bfloat162float(h1));
    union { __nv_bfloat16 h[2]; uint32_t u; } hv, lv;
    hv.h[0] = h0; hv.h[1] = h1;
    lv.h[0] = l0; lv.h[1] = l1;
    lo_out = lv.u;
    return hv.u;
}

// ---------------------------------------------------------------------------
// Kernel 1: build split-bf16 transposed basis  C^T[n][k] with row layout
//   [Ch(512) | Ch(512) | Cl(512)]
//   C[k][2r]   =  cos(2*pi*k*r/512) * filt[r]
//   C[k][2r+1] = -sin(2*pi*k*r/512) * filt[r]
// ---------------------------------------------------------------------------
__global__ void build_basis_t(const float* __restrict__ filt) {
    int idx = blockIdx.x * blockDim.x + threadIdx.x; // 0 .. 256*512-1
    int n = idx >> 9;        // 0..255
    int k = idx & 511;       // 0..511
    int r = n >> 1;
    int phase = (k * r) & (DIM - 1);
    float ang = (float)phase * (6.283185307179586f / (float)DIM);
    float s, co;
    sincosf(ang, &s, &co);
    float v = ((n & 1) ? -s : co) * filt[r];
    __nv_bfloat16 h = __float2bfloat16(v);
    __nv_bfloat16 l = __float2bfloat16(v - __bfloat162float(h));
    size_t base = (size_t)n * FEATX;
    g_bsplit[base + k]            = h;
    g_bsplit[base + DIM + k]      = h;
    g_bsplit[base + 2 * DIM + k]  = l;
}

// ---------------------------------------------------------------------------
// Kernel 2: convert x,y (fp32) to split-bf16 rows [Xh | Xl | Xh], K=1536
// ---------------------------------------------------------------------------
__global__ __launch_bounds__(256) void convert_split(const float* __restrict__ x,
                                                     const float* __restrict__ y) {
    const float* __restrict__ src = blockIdx.z ? y : x;
    __nv_bfloat16* __restrict__ dst = blockIdx.z ? g_ys : g_xs;

    int idx = blockIdx.x * blockDim.x + threadIdx.x; // one float4 each
    int m  = idx >> 7;            // DIM/4 = 128 float4 per row
    int c4 = (idx & 127) * 4;
    float4 v = *(const float4*)&src[(size_t)m * DIM + c4];

    uint32_t l01, l23;
    uint32_t h01 = split_pair(v.x, v.y, l01);
    uint32_t h23 = split_pair(v.z, v.w, l23);
    uint2 hv = make_uint2(h01, h23);
    uint2 lv = make_uint2(l01, l23);

    size_t base = (size_t)m * FEATX + c4;
    *(uint2*)&dst[base]            = hv;
    *(uint2*)&dst[base + DIM]      = lv;
    *(uint2*)&dst[base + 2 * DIM]  = hv;
}

// ---------------------------------------------------------------------------
// Kernel 3: feature GEMM on tensor cores (NT, bf16, fp32 accum), K = 1536
//   F[m,n] = dot(Xext[m,0:1536], CextT[n,0:1536])  (3-term split product)
// Same tile structure as gram_mma; epilogue splits F into bf16 hi/lo and
// stores gram features:  x -> [hi|lo|hi],  y -> [hi|hi|lo].
// ---------------------------------------------------------------------------
#define KC   32
#define LDSM 40   // padded row length in bf16 (80B stride: conflict-free)

__global__ __launch_bounds__(256, 2) void feat_mma() {
    __shared__ __nv_bfloat16 As[2][128 * LDSM]; // X rows (m)
    __shared__ __nv_bfloat16 Bs[2][128 * LDSM]; // C^T rows (n)

    const int tid  = threadIdx.x;
    const int wid  = tid >> 5;
    const int lane = tid & 31;

    const int isY = blockIdx.z;
    const __nv_bfloat16* Ag = isY ? g_ys : g_xs;
    const __nv_bfloat16* Bg = g_bsplit;
    __nv_bfloat16* __restrict__ dst = isY ? g_fy : g_fx;

    const int j0 = blockIdx.x * 128;  // n-tile (0 or 128)
    const int i0 = blockIdx.y * 128;  // m-tile

    const int i0w = (wid & 3) * 32;
    const int j0w = (wid >> 2) * 64;

    const int rowL = tid >> 2;
    const int c16  = (tid & 3) * 8;

    const uint32_t aSm = smem_to_u32(As);
    const uint32_t bSm = smem_to_u32(Bs);
    const uint32_t stageB = 128 * LDSM * 2;

    float acc[2][8][4];
#pragma unroll
    for (int ti = 0; ti < 2; ti++)
#pragma unroll
        for (int tj = 0; tj < 8; tj++)
#pragma unroll
            for (int q = 0; q < 4; q++) acc[ti][tj][q] = 0.0f;

    {
        uint4 ra0 = *(const uint4*)&Ag[(size_t)(i0 + rowL) * FEATX + c16];
        uint4 ra1 = *(const uint4*)&Ag[(size_t)(i0 + rowL + 64) * FEATX + c16];
        uint4 rb0 = *(const uint4*)&Bg[(size_t)(j0 + rowL) * FEATX + c16];
        uint4 rb1 = *(const uint4*)&Bg[(size_t)(j0 + rowL + 64) * FEATX + c16];
        *(uint4*)&As[0][rowL * LDSM + c16] = ra0;
        *(uint4*)&As[0][(rowL + 64) * LDSM + c16] = ra1;
        *(uint4*)&Bs[0][rowL * LDSM + c16] = rb0;
        *(uint4*)&Bs[0][(rowL + 64) * LDSM + c16] = rb1;
    }
    __syncthreads();

    int buf = 0;
    for (int s = 0; s < FEATX / KC; s++) {
        uint4 ra0, ra1, rb0, rb1;
        const int kn = (s + 1) * KC;
        if (kn < FEATX) {
            ra0 = *(const uint4*)&Ag[(size_t)(i0 + rowL) * FEATX + kn + c16];
            ra1 = *(const uint4*)&Ag[(size_t)(i0 + rowL + 64) * FEATX + kn + c16];
            rb0 = *(const uint4*)&Bg[(size_t)(j0 + rowL) * FEATX + kn + c16];
            rb1 = *(const uint4*)&Bg[(size_t)(j0 + rowL + 64) * FEATX + kn + c16];
        }

        const uint32_t aBase = aSm + buf * stageB;
        const uint32_t bBase = bSm + buf * stageB;
#pragma unroll
        for (int ks = 0; ks < 2; ks++) {
            uint32_t af[2][4];
#pragma unroll
            for (int ti = 0; ti < 2; ti++) {
                int row = i0w + ti * 16 + (lane & 15);
                uint32_t off = (uint32_t)(row * LDSM + ks * 16 + ((lane >> 4) << 3)) * 2;
                ldsm4(aBase + off, af[ti]);
            }
#pragma unroll
            for (int tp = 0; tp < 4; tp++) {
                uint32_t bf[4];
                int row = j0w + tp * 16 + ((lane >> 4) << 3) + (lane & 7);
                uint32_t off = (uint32_t)(row * LDSM + ks * 16 + (((lane >> 3) & 1) << 3)) * 2;
                ldsm4(bBase + off, bf);
#pragma unroll
                for (int ti = 0; ti < 2; ti++) {
                    mma16816(acc[ti][tp * 2], af[ti], bf[0], bf[1]);
                    mma16816(acc[ti][tp * 2 + 1], af[ti], bf[2], bf[3]);
                }
            }
        }

        if (kn < FEATX) {
            const int nb = buf ^ 1;
            *(uint4*)&As[nb][rowL * LDSM + c16] = ra0;
            *(uint4*)&As[nb][(rowL + 64) * LDSM + c16] = ra1;
            *(uint4*)&Bs[nb][rowL * LDSM + c16] = rb0;
            *(uint4*)&Bs[nb][(rowL + 64) * LDSM + c16] = rb1;
        }
        __syncthreads();
        buf ^= 1;
    }

    // Epilogue: split features into bf16 hi/lo, store 3 segments per row.
#pragma unroll
    for (int ti = 0; ti < 2; ti++) {
#pragma unroll
        for (int tj = 0; tj < 8; tj++) {
            int i = i0 + i0w + ti * 16 + (lane >> 2);
            int j = j0 + j0w + tj * 8 + (lane & 3) * 2;
#pragma unroll
            for (int half = 0; half < 2; half++) {
                int m = i + half * 8;
                uint32_t lv;
                uint32_t hv = split_pair(acc[ti][tj][half * 2],
                                         acc[ti][tj][half * 2 + 1], lv);
                size_t base = (size_t)m * FEAT3 + j;
                *(uint32_t*)&dst[base]            = hv;             // seg0: hi
                *(uint32_t*)&dst[base + FEAT]     = isY ? hv : lv;  // seg1
                *(uint32_t*)&dst[base + 2 * FEAT] = isY ? lv : hv;  // seg2
            }
        }
    }
}

// ---------------------------------------------------------------------------
// Kernel 4: batched Gram GEMM via mma.sync (bf16, fp32 accum), K = 768
// (byte-identical to the R11 passing kernel)
// ---------------------------------------------------------------------------
__global__ __launch_bounds__(256, 2) void gram_mma(float* __restrict__ out) {
    __shared__ __nv_bfloat16 As[2][128 * LDSM]; // Fx tile (i rows)
    __shared__ __nv_bfloat16 Bs[2][128 * LDSM]; // Fy tile (j rows)

    const int tid  = threadIdx.x;
    const int wid  = tid >> 5;
    const int lane = tid & 31;

    const int b  = blockIdx.z;
    const int j0 = blockIdx.x * 128;
    const int i0 = blockIdx.y * 128;

    const __nv_bfloat16* Ag = g_fx + (size_t)b * NROWS * FEAT3;
    const __nv_bfloat16* Bg = g_fy + (size_t)b * NROWS * FEAT3;

    const int i0w = (wid & 3) * 32;
    const int j0w = (wid >> 2) * 64;

    const int rowL = tid >> 2;
    const int c16  = (tid & 3) * 8;

    const uint32_t aSm = smem_to_u32(As);
    const uint32_t bSm = smem_to_u32(Bs);
    const uint32_t stageB = 128 * LDSM * 2;

    float acc[2][8][4];
#pragma unroll
    for (int ti = 0; ti < 2; ti++)
#pragma unroll
        for (int tj = 0; tj < 8; tj++)
#pragma unroll
            for (int q = 0; q < 4; q++) acc[ti][tj][q] = 0.0f;

    {
        uint4 ra0 = *(const uint4*)&Ag[(size_t)(i0 + rowL) * FEAT3 + c16];
        uint4 ra1 = *(const uint4*)&Ag[(size_t)(i0 + rowL + 64) * FEAT3 + c16];
        uint4 rb0 = *(const uint4*)&Bg[(size_t)(j0 + rowL) * FEAT3 + c16];
        uint4 rb1 = *(const uint4*)&Bg[(size_t)(j0 + rowL + 64) * FEAT3 + c16];
        *(uint4*)&As[0][rowL * LDSM + c16] = ra0;
        *(uint4*)&As[0][(rowL + 64) * LDSM + c16] = ra1;
        *(uint4*)&Bs[0][rowL * LDSM + c16] = rb0;
        *(uint4*)&Bs[0][(rowL + 64) * LDSM + c16] = rb1;
    }
    __syncthreads();

    int buf = 0;
    for (int s = 0; s < FEAT3 / KC; s++) {
        uint4 ra0, ra1, rb0, rb1;
        const int kn = (s + 1) * KC;
        if (kn < FEAT3) {
            ra0 = *(const uint4*)&Ag[(size_t)(i0 + rowL) * FEAT3 + kn + c16];
            ra1 = *(const uint4*)&Ag[(size_t)(i0 + rowL + 64) * FEAT3 + kn + c16];
            rb0 = *(const uint4*)&Bg[(size_t)(j0 + rowL) * FEAT3 + kn + c16];
            rb1 = *(const uint4*)&Bg[(size_t)(j0 + rowL + 64) * FEAT3 + kn + c16];
        }

        const uint32_t aBase = aSm + buf * stageB;
        const uint32_t bBase = bSm + buf * stageB;
#pragma unroll
        for (int ks = 0; ks < 2; ks++) {
            uint32_t af[2][4];
#pragma unroll
            for (int ti = 0; ti < 2; ti++) {
                int row = i0w + ti * 16 + (lane & 15);
                uint32_t off = (uint32_t)(row * LDSM + ks * 16 + ((lane >> 4) << 3)) * 2;
                ldsm4(aBase + off, af[ti]);
            }
#pragma unroll
            for (int tp = 0; tp < 4; tp++) {
                uint32_t bf[4];
                int row = j0w + tp * 16 + ((lane >> 4) << 3) + (lane & 7);
                uint32_t off = (uint32_t)(row * LDSM + ks * 16 + (((lane >> 3) & 1) << 3)) * 2;
                ldsm4(bBase + off, bf);
#pragma unroll
                for (int ti = 0; ti < 2; ti++) {
                    mma16816(acc[ti][tp * 2], af[ti], bf[0], bf[1]);
                    mma16816(acc[ti][tp * 2 + 1], af[ti], bf[2], bf[3]);
                }
            }
        }

        if (kn < FEAT3) {
            const int nb = buf ^ 1;
            *(uint4*)&As[nb][rowL * LDSM + c16] = ra0;
            *(uint4*)&As[nb][(rowL + 64) * LDSM + c16] = ra1;
            *(uint4*)&Bs[nb][rowL * LDSM + c16] = rb0;
            *(uint4*)&Bs[nb][(rowL + 64) * LDSM + c16] = rb1;
        }
        __syncthreads();
        buf ^= 1;
    }

    const float scale = 1.0f / (float)RANK;
#pragma unroll
    for (int ti = 0; ti < 2; ti++) {
#pragma unroll
        for (int tj = 0; tj < 8; tj++) {
            int i = i0 + i0w + ti * 16 + (lane >> 2);
            int j = j0 + j0w + tj * 8 + (lane & 3) * 2;
            size_t base = ((size_t)b * NROWS + i) * NROWS + j;
            float2 v0 = make_float2(acc[ti][tj][0] * scale, acc[ti][tj][1] * scale);
            float2 v1 = make_float2(acc[ti][tj][2] * scale, acc[ti][tj][3] * scale);
            *(float2*)&out[base] = v0;
            *(float2*)&out[base + (size_t)8 * NROWS] = v1;
        }
    }
}

// ---------------------------------------------------------------------------
extern "C" void kernel_launch(void* const* d_in, const int* in_sizes, int n_in,
                              void* d_out, int out_size) {
    const float* x    = (const float*)d_in[0];
    const float* y    = (const float*)d_in[1];
    const float* filt = (const float*)d_in[2];
    float* out = (float*)d_out;

    // 1) split transposed basis (256 x 1536 bf16)
    build_basis_t<<<FEAT * DIM / 256, 256>>>(filt);

    // 2) split x,y to bf16 [h|l|h] rows (K=1536)
    dim3 cgrid(MTOT * DIM / 4 / 256, 1, 2);
    convert_split<<<cgrid, 256>>>(x, y);

    // 3) feature GEMM on tensor cores -> gram features [hi|lo|hi]/[hi|hi|lo]
    dim3 fgrid(FEAT / 128, MTOT / 128, 2);
    feat_mma<<<fgrid, 256>>>();

    // 4) batched Gram on tensor cores (K=768)
    dim3 ggrid(NROWS / 128, NROWS / 128, BATCH);
    gram_mma<<<ggrid, 256>>>(out);
}

// round 15
// speedup vs baseline: 2.2599x; 1.0663x over previous
#include <cuda_runtime.h>
#include <cuda_bf16.h>
#include <cstdint>

// Problem shape (fixed by the dataset):
//   x, y : (4, 4096, 512) float32
//   filt : (128,)         float32
//   out  : (4, 4096, 4096) float32
#define BATCH 4
#define NROWS 4096
#define DIM   512
#define RANK  128
#define FEAT  256    // 2*RANK (re/im interleaved)
// Gram feature encoding (verified R11/R12):
//   x rows: [hx(256) | lx(256) | hx(256)]
//   y rows: [hy(256) | hy(256) | ly(256)]
//   dot_768 = hx.hy + lx.hy + hx.ly   (only lx.ly dropped)
#define FEAT3 768
// Feature-GEMM input encoding (same trick on X and basis):
//   X rows:   [Xh(512) | Xl(512) | Xh(512)]
//   C^T rows: [Ch(512) | Ch(512) | Cl(512)]
#define FEATX 1536
#define MTOT  (BATCH * NROWS)

// Scratch (device globals: no allocation allowed in kernel_launch)
__device__ __nv_bfloat16 g_bsplit[FEAT * FEATX];       // 768 KB  C^T split
__device__ __nv_bfloat16 g_xs[MTOT * FEATX];           // 48 MB   X split
__device__ __nv_bfloat16 g_ys[MTOT * FEATX];           // 48 MB   Y split
__device__ __nv_bfloat16 g_fx[MTOT * FEAT3];           // 24 MB   features x
__device__ __nv_bfloat16 g_fy[MTOT * FEAT3];           // 24 MB   features y

// ---------------------------------------------------------------------------
// helpers
// ---------------------------------------------------------------------------
__device__ __forceinline__ uint32_t smem_to_u32(const void* p) {
    uint32_t a;
    asm("{ .reg .u64 t; cvta.to.shared.u64 t, %1; cvt.u32.u64 %0, t; }"
        : "=r"(a) : "l"(p));
    return a;
}

#define CP_ASYNC16(smem_u32, gptr) \
    asm volatile("cp.async.cg.shared.global [%0], [%1], 16;" \
                 :: "r"(smem_u32), "l"(gptr) : "memory")
#define CP_COMMIT() asm volatile("cp.async.commit_group;" ::: "memory")
#define CP_WAIT0()  asm volatile("cp.async.wait_group 0;" ::: "memory")

__device__ __forceinline__ void ldsm4(uint32_t addr, uint32_t* r) {
    asm volatile("ldmatrix.sync.aligned.m8n8.x4.shared.b16 {%0,%1,%2,%3}, [%4];"
                 : "=r"(r[0]), "=r"(r[1]), "=r"(r[2]), "=r"(r[3]) : "r"(addr));
}

__device__ __forceinline__ void mma16816(float* c, const uint32_t* a,
                                         uint32_t b0, uint32_t b1) {
    asm volatile(
        "mma.sync.aligned.m16n8k16.row.col.f32.bf16.bf16.f32 "
        "{%0,%1,%2,%3}, {%4,%5,%6,%7}, {%8,%9}, {%0,%1,%2,%3};"
        : "+f"(c[0]), "+f"(c[1]), "+f"(c[2]), "+f"(c[3])
        : "r"(a[0]), "r"(a[1]), "r"(a[2]), "r"(a[3]), "r"(b0), "r"(b1));
}

__device__ __forceinline__ uint32_t split_pair(float f0, float f1, uint32_t& lo_out) {
    __nv_bfloat16 h0 = __float2bfloat16(f0);
    __nv_bfloat16 h1 = __float2bfloat16(f1);
    __nv_bfloat16 l0 = __float2bfloat16(f0 - __bfloat162float(h0));
    __nv_bfloat16 l1 = __float2bfloat16(f1 - __bfloat162float(h1));
    union { __nv_bfloat16 h[2]; uint32_t u; } hv, lv;
    hv.h[0] = h0; hv.h[1] = h1;
    lv.h[0] = l0; lv.h[1] = l1;
    lo_out = lv.u;
    return hv.u;
}

// ---------------------------------------------------------------------------
// Kernel 1: build split-bf16 transposed basis  C^T[n][k], rows [Ch|Ch|Cl]
// ---------------------------------------------------------------------------
__global__ void build_basis_t(const float* __restrict__ filt) {
    int idx = blockIdx.x * blockDim.x + threadIdx.x; // 0 .. 256*512-1
    int n = idx >> 9;        // 0..255
    int k = idx & 511;       // 0..511
    int r = n >> 1;
    int phase = (k * r) & (DIM - 1);
    float ang = (float)phase * (6.283185307179586f / (float)DIM);
    float s, co;
    sincosf(ang, &s, &co);
    float v = ((n & 1) ? -s : co) * filt[r];
    __nv_bfloat16 h = __float2bfloat16(v);
    __nv_bfloat16 l = __float2bfloat16(v - __bfloat162float(h));
    size_t base = (size_t)n * FEATX;
    g_bsplit[base + k]            = h;
    g_bsplit[base + DIM + k]      = h;
    g_bsplit[base + 2 * DIM + k]  = l;
}

// ---------------------------------------------------------------------------
// Kernel 2: convert x,y (fp32) to split-bf16 rows [Xh | Xl | Xh], K=1536
// ---------------------------------------------------------------------------
__global__ __launch_bounds__(256) void convert_split(const float* __restrict__ x,
                                                     const float* __restrict__ y) {
    const float* __restrict__ src = blockIdx.z ? y : x;
    __nv_bfloat16* __restrict__ dst = blockIdx.z ? g_ys : g_xs;

    int idx = blockIdx.x * blockDim.x + threadIdx.x; // one float4 each
    int m  = idx >> 7;            // DIM/4 = 128 float4 per row
    int c4 = (idx & 127) * 4;
    float4 v = *(const float4*)&src[(size_t)m * DIM + c4];

    uint32_t l01, l23;
    uint32_t h01 = split_pair(v.x, v.y, l01);
    uint32_t h23 = split_pair(v.z, v.w, l23);
    uint2 hv = make_uint2(h01, h23);
    uint2 lv = make_uint2(l01, l23);

    size_t base = (size_t)m * FEATX + c4;
    *(uint2*)&dst[base]            = hv;
    *(uint2*)&dst[base + DIM]      = lv;
    *(uint2*)&dst[base + 2 * DIM]  = hv;
}

// ---------------------------------------------------------------------------
// Shared tile-GEMM config: CTA 128x128, 8 warps = 4(i) x 2(j), warp 32x64,
// kc=32 double-buffered smem, pad 40 bf16/row (80B: conflict-free ldmatrix).
// Tile loads via cp.async (no LDG->reg->STS roundtrip through L1).
// ---------------------------------------------------------------------------
#define KC   32
#define LDSM 40   // padded row length in bf16

// Issues the 4 cp.async loads (A row, A row+64, B row, B row+64) for one stage
#define ISSUE_STAGE(aBaseU32, bBaseU32, Aptr, Bptr, stride, i0_, j0_, kofs)     \
    do {                                                                        \
        uint32_t so = (uint32_t)(rowL * LDSM + c16) * 2;                        \
        uint32_t so64 = so + (uint32_t)(64 * LDSM) * 2;                         \
        CP_ASYNC16((aBaseU32) + so,   &(Aptr)[(size_t)((i0_) + rowL) * (stride) + (kofs) + c16]); \
        CP_ASYNC16((aBaseU32) + so64, &(Aptr)[(size_t)((i0_) + rowL + 64) * (stride) + (kofs) + c16]); \
        CP_ASYNC16((bBaseU32) + so,   &(Bptr)[(size_t)((j0_) + rowL) * (stride) + (kofs) + c16]); \
        CP_ASYNC16((bBaseU32) + so64, &(Bptr)[(size_t)((j0_) + rowL + 64) * (stride) + (kofs) + c16]); \
        CP_COMMIT();                                                            \
    } while (0)

// ---------------------------------------------------------------------------
// Kernel 3: feature GEMM on tensor cores (NT, bf16, fp32 accum), K = 1536
//   F[m,n] = dot(Xext[m,:], CextT[n,:]); epilogue stores gram features
//   x -> [hi|lo|hi],  y -> [hi|hi|lo].
// ---------------------------------------------------------------------------
__global__ __launch_bounds__(256, 2) void feat_mma() {
    __shared__ __nv_bfloat16 As[2][128 * LDSM];
    __shared__ __nv_bfloat16 Bs[2][128 * LDSM];

    const int tid  = threadIdx.x;
    const int wid  = tid >> 5;
    const int lane = tid & 31;

    const int isY = blockIdx.z;
    const __nv_bfloat16* Ag = isY ? g_ys : g_xs;
    const __nv_bfloat16* Bg = g_bsplit;
    __nv_bfloat16* __restrict__ dst = isY ? g_fy : g_fx;

    const int j0 = blockIdx.x * 128;
    const int i0 = blockIdx.y * 128;

    const int i0w = (wid & 3) * 32;
    const int j0w = (wid >> 2) * 64;

    const int rowL = tid >> 2;
    const int c16  = (tid & 3) * 8;

    const uint32_t aSm = smem_to_u32(As);
    const uint32_t bSm = smem_to_u32(Bs);
    const uint32_t stageB = 128 * LDSM * 2;

    float acc[2][8][4];
#pragma unroll
    for (int ti = 0; ti < 2; ti++)
#pragma unroll
        for (int tj = 0; tj < 8; tj++)
#pragma unroll
            for (int q = 0; q < 4; q++) acc[ti][tj][q] = 0.0f;

    ISSUE_STAGE(aSm, bSm, Ag, Bg, FEATX, i0, j0, 0);
    CP_WAIT0();
    __syncthreads();

    int buf = 0;
    for (int s = 0; s < FEATX / KC; s++) {
        const int kn = (s + 1) * KC;
        if (kn < FEATX) {
            const int nb = buf ^ 1;
            ISSUE_STAGE(aSm + nb * stageB, bSm + nb * stageB, Ag, Bg, FEATX,
                        i0, j0, kn);
        }

        const uint32_t aBase = aSm + buf * stageB;
        const uint32_t bBase = bSm + buf * stageB;
#pragma unroll
        for (int ks = 0; ks < 2; ks++) {
            uint32_t af[2][4];
#pragma unroll
            for (int ti = 0; ti < 2; ti++) {
                int row = i0w + ti * 16 + (lane & 15);
                uint32_t off = (uint32_t)(row * LDSM + ks * 16 + ((lane >> 4) << 3)) * 2;
                ldsm4(aBase + off, af[ti]);
            }
#pragma unroll
            for (int tp = 0; tp < 4; tp++) {
                uint32_t bf[4];
                int row = j0w + tp * 16 + ((lane >> 4) << 3) + (lane & 7);
                uint32_t off = (uint32_t)(row * LDSM + ks * 16 + (((lane >> 3) & 1) << 3)) * 2;
                ldsm4(bBase + off, bf);
#pragma unroll
                for (int ti = 0; ti < 2; ti++) {
                    mma16816(acc[ti][tp * 2], af[ti], bf[0], bf[1]);
                    mma16816(acc[ti][tp * 2 + 1], af[ti], bf[2], bf[3]);
                }
            }
        }

        CP_WAIT0();
        __syncthreads();
        buf ^= 1;
    }

    // Epilogue: split features into bf16 hi/lo, store 3 segments per row.
#pragma unroll
    for (int ti = 0; ti < 2; ti++) {
#pragma unroll
        for (int tj = 0; tj < 8; tj++) {
            int i = i0 + i0w + ti * 16 + (lane >> 2);
            int j = j0 + j0w + tj * 8 + (lane & 3) * 2;
#pragma unroll
            for (int half = 0; half < 2; half++) {
                int m = i + half * 8;
                uint32_t lv;
                uint32_t hv = split_pair(acc[ti][tj][half * 2],
                                         acc[ti][tj][half * 2 + 1], lv);
                size_t base = (size_t)m * FEAT3 + j;
                *(uint32_t*)&dst[base]            = hv;             // seg0: hi
                *(uint32_t*)&dst[base + FEAT]     = isY ? hv : lv;  // seg1
                *(uint32_t*)&dst[base + 2 * FEAT] = isY ? lv : hv;  // seg2
            }
        }
    }
}

// ---------------------------------------------------------------------------
// Kernel 4: batched Gram GEMM via mma.sync (bf16, fp32 accum), K = 768
// ---------------------------------------------------------------------------
__global__ __launch_bounds__(256, 2) void gram_mma(float* __restrict__ out) {
    __shared__ __nv_bfloat16 As[2][128 * LDSM];
    __shared__ __nv_bfloat16 Bs[2][128 * LDSM];

    const int tid  = threadIdx.x;
    const int wid  = tid >> 5;
    const int lane = tid & 31;

    const int b  = blockIdx.z;
    const int j0 = blockIdx.x * 128;
    const int i0 = blockIdx.y * 128;

    const __nv_bfloat16* Ag = g_fx + (size_t)b * NROWS * FEAT3;
    const __nv_bfloat16* Bg = g_fy + (size_t)b * NROWS * FEAT3;

    const int i0w = (wid & 3) * 32;
    const int j0w = (wid >> 2) * 64;

    const int rowL = tid >> 2;
    const int c16  = (tid & 3) * 8;

    const uint32_t aSm = smem_to_u32(As);
    const uint32_t bSm = smem_to_u32(Bs);
    const uint32_t stageB = 128 * LDSM * 2;

    float acc[2][8][4];
#pragma unroll
    for (int ti = 0; ti < 2; ti++)
#pragma unroll
        for (int tj = 0; tj < 8; tj++)
#pragma unroll
            for (int q = 0; q < 4; q++) acc[ti][tj][q] = 0.0f;

    ISSUE_STAGE(aSm, bSm, Ag, Bg, FEAT3, i0, j0, 0);
    CP_WAIT0();
    __syncthreads();

    int buf = 0;
    for (int s = 0; s < FEAT3 / KC; s++) {
        const int kn = (s + 1) * KC;
        if (kn < FEAT3) {
            const int nb = buf ^ 1;
            ISSUE_STAGE(aSm + nb * stageB, bSm + nb * stageB, Ag, Bg, FEAT3,
                        i0, j0, kn);
        }

        const uint32_t aBase = aSm + buf * stageB;
        const uint32_t bBase = bSm + buf * stageB;
#pragma unroll
        for (int ks = 0; ks < 2; ks++) {
            uint32_t af[2][4];
#pragma unroll
            for (int ti = 0; ti < 2; ti++) {
                int row = i0w + ti * 16 + (lane & 15);
                uint32_t off = (uint32_t)(row * LDSM + ks * 16 + ((lane >> 4) << 3)) * 2;
                ldsm4(aBase + off, af[ti]);
            }
#pragma unroll
            for (int tp = 0; tp < 4; tp++) {
                uint32_t bf[4];
                int row = j0w + tp * 16 + ((lane >> 4) << 3) + (lane & 7);
                uint32_t off = (uint32_t)(row * LDSM + ks * 16 + (((lane >> 3) & 1) << 3)) * 2;
                ldsm4(bBase + off, bf);
#pragma unroll
                for (int ti = 0; ti < 2; ti++) {
                    mma16816(acc[ti][tp * 2], af[ti], bf[0], bf[1]);
                    mma16816(acc[ti][tp * 2 + 1], af[ti], bf[2], bf[3]);
                }
            }
        }

        CP_WAIT0();
        __syncthreads();
        buf ^= 1;
    }

    const float scale = 1.0f / (float)RANK;
#pragma unroll
    for (int ti = 0; ti < 2; ti++) {
#pragma unroll
        for (int tj = 0; tj < 8; tj++) {
            int i = i0 + i0w + ti * 16 + (lane >> 2);
            int j = j0 + j0w + tj * 8 + (lane & 3) * 2;
            size_t base = ((size_t)b * NROWS + i) * NROWS + j;
            float2 v0 = make_float2(acc[ti][tj][0] * scale, acc[ti][tj][1] * scale);
            float2 v1 = make_float2(acc[ti][tj][2] * scale, acc[ti][tj][3] * scale);
            *(float2*)&out[base] = v0;
            *(float2*)&out[base + (size_t)8 * NROWS] = v1;
        }
    }
}

// ---------------------------------------------------------------------------
extern "C" void kernel_launch(void* const* d_in, const int* in_sizes, int n_in,
                              void* d_out, int out_size) {
    const float* x    = (const float*)d_in[0];
    const float* y    = (const float*)d_in[1];
    const float* filt = (const float*)d_in[2];
    float* out = (float*)d_out;

    // 1) split transposed basis (256 x 1536 bf16)
    build_basis_t<<<FEAT * DIM / 256, 256>>>(filt);

    // 2) split x,y to bf16 [h|l|h] rows (K=1536)
    dim3 cgrid(MTOT * DIM / 4 / 256, 1, 2);
    convert_split<<<cgrid, 256>>>(x, y);

    // 3) feature GEMM on tensor cores -> gram features [hi|lo|hi]/[hi|hi|lo]
    dim3 fgrid(FEAT / 128, MTOT / 128, 2);
    feat_mma<<<fgrid, 256>>>();

    // 4) batched Gram on tensor cores (K=768)
    dim3 ggrid(NROWS / 128, NROWS / 128, BATCH);
    gram_mma<<<ggrid, 256>>>(out);
}

// round 17
// speedup vs baseline: 2.5189x; 1.1146x over previous
#include <cuda_runtime.h>
#include <cuda_bf16.h>
#include <cstdint>

// Problem shape (fixed by the dataset):
//   x, y : (4, 4096, 512) float32
//   filt : (128,)         float32
//   out  : (4, 4096, 4096) float32
#define BATCH 4
#define NROWS 4096
#define DIM   512
#define RANK  128
#define FEAT  256    // 2*RANK (re/im interleaved)
// Gram feature encoding (verified R11/R12/R15):
//   x rows: [hx(256) | lx(256) | hx(256)]
//   y rows: [hy(256) | hy(256) | ly(256)]
//   dot_768 = hx.hy + lx.hy + hx.ly   (only lx.ly dropped)
#define FEAT3 768
// Feature-GEMM input encoding (same trick on X and basis):
//   X rows:   [Xh(512) | Xl(512) | Xh(512)]
//   C^T rows: [Ch(512) | Ch(512) | Cl(512)]
#define FEATX 1536
#define MTOT  (BATCH * NROWS)

// Scratch (device globals: no allocation allowed in kernel_launch)
__device__ __nv_bfloat16 g_bsplit[FEAT * FEATX];       // 768 KB  C^T split
__device__ __nv_bfloat16 g_xs[MTOT * FEATX];           // 48 MB   X split
__device__ __nv_bfloat16 g_ys[MTOT * FEATX];           // 48 MB   Y split
__device__ __nv_bfloat16 g_fx[MTOT * FEAT3];           // 24 MB   features x
__device__ __nv_bfloat16 g_fy[MTOT * FEAT3];           // 24 MB   features y

// ---------------------------------------------------------------------------
// helpers
// ---------------------------------------------------------------------------
__device__ __forceinline__ uint32_t smem_to_u32(const void* p) {
    uint32_t a;
    asm("{ .reg .u64 t; cvta.to.shared.u64 t, %1; cvt.u32.u64 %0, t; }"
        : "=r"(a) : "l"(p));
    return a;
}

#define CP_ASYNC16(smem_u32, gptr) \
    asm volatile("cp.async.cg.shared.global [%0], [%1], 16;" \
                 :: "r"(smem_u32), "l"(gptr) : "memory")
#define CP_COMMIT() asm volatile("cp.async.commit_group;" ::: "memory")
#define CP_WAIT0()  asm volatile("cp.async.wait_group 0;" ::: "memory")

__device__ __forceinline__ void ldsm4(uint32_t addr, uint32_t* r) {
    asm volatile("ldmatrix.sync.aligned.m8n8.x4.shared.b16 {%0,%1,%2,%3}, [%4];"
                 : "=r"(r[0]), "=r"(r[1]), "=r"(r[2]), "=r"(r[3]) : "r"(addr));
}

__device__ __forceinline__ void mma16816(float* c, const uint32_t* a,
                                         uint32_t b0, uint32_t b1) {
    asm volatile(
        "mma.sync.aligned.m16n8k16.row.col.f32.bf16.bf16.f32 "
        "{%0,%1,%2,%3}, {%4,%5,%6,%7}, {%8,%9}, {%0,%1,%2,%3};"
        : "+f"(c[0]), "+f"(c[1]), "+f"(c[2]), "+f"(c[3])
        : "r"(a[0]), "r"(a[1]), "r"(a[2]), "r"(a[3]), "r"(b0), "r"(b1));
}

__device__ __forceinline__ uint32_t split_pair(float f0, float f1, uint32_t& lo_out) {
    __nv_bfloat16 h0 = __float2bfloat16(f0);
    __nv_bfloat16 h1 = __float2bfloat16(f1);
    __nv_bfloat16 l0 = __float2bfloat16(f0 - __bfloat162float(h0));
    __nv_bfloat16 l1 = __float2bfloat16(f1 - __bfloat162float(h1));
    union { __nv_bfloat16 h[2]; uint32_t u; } hv, lv;
    hv.h[0] = h0; hv.h[1] = h1;
    lv.h[0] = l0; lv.h[1] = l1;
    lo_out = lv.u;
    return hv.u;
}

// ---------------------------------------------------------------------------
// Kernel 1: build split-bf16 transposed basis  C^T[n][k], rows [Ch|Ch|Cl]
// ---------------------------------------------------------------------------
__global__ void build_basis_t(const float* __restrict__ filt) {
    int idx = blockIdx.x * blockDim.x + threadIdx.x; // 0 .. 256*512-1
    int n = idx >> 9;        // 0..255
    int k = idx & 511;       // 0..511
    int r = n >> 1;
    int phase = (k * r) & (DIM - 1);
    float ang = (float)phase * (6.283185307179586f / (float)DIM);
    float s, co;
    sincosf(ang, &s, &co);
    float v = ((n & 1) ? -s : co) * filt[r];
    __nv_bfloat16 h = __float2bfloat16(v);
    __nv_bfloat16 l = __float2bfloat16(v - __bfloat162float(h));
    size_t base = (size_t)n * FEATX;
    g_bsplit[base + k]            = h;
    g_bsplit[base + DIM + k]      = h;
    g_bsplit[base + 2 * DIM + k]  = l;
}

// ---------------------------------------------------------------------------
// Kernel 2: convert x,y (fp32) to split-bf16 rows [Xh | Xl | Xh], K=1536
// ---------------------------------------------------------------------------
__global__ __launch_bounds__(256) void convert_split(const float* __restrict__ x,
                                                     const float* __restrict__ y) {
    const float* __restrict__ src = blockIdx.z ? y : x;
    __nv_bfloat16* __restrict__ dst = blockIdx.z ? g_ys : g_xs;

    int idx = blockIdx.x * blockDim.x + threadIdx.x; // one float4 each
    int m  = idx >> 7;            // DIM/4 = 128 float4 per row
    int c4 = (idx & 127) * 4;
    float4 v = *(const float4*)&src[(size_t)m * DIM + c4];

    uint32_t l01, l23;
    uint32_t h01 = split_pair(v.x, v.y, l01);
    uint32_t h23 = split_pair(v.z, v.w, l23);
    uint2 hv = make_uint2(h01, h23);
    uint2 lv = make_uint2(l01, l23);

    size_t base = (size_t)m * FEATX + c4;
    *(uint2*)&dst[base]            = hv;
    *(uint2*)&dst[base + DIM]      = lv;
    *(uint2*)&dst[base + 2 * DIM]  = hv;
}

// ---------------------------------------------------------------------------
// Shared tile-GEMM config: CTA 128x128, 8 warps = 4(i) x 2(j), warp 32x64.
// KC=64 double-buffered smem (12 stages for gram, 24 for feat): half the
// barrier count of KC=32 and a 2x cp.async latency-hiding window.
// Row padded to 72 bf16 (144B stride): ldmatrix 8-row address lanes land on
// byte offsets {0,16,32,...,112} mod 128 -> conflict-free.
// Dynamic smem: 4 * 128*72*2 = 73728 B per CTA (2 CTAs/SM).
// ---------------------------------------------------------------------------
#define KC    64
#define LDSMK 72   // padded row length in bf16
#define STAGE_B (128 * LDSMK * 2)          // bytes per operand per stage
#define SMEM_TOTAL (4 * STAGE_B)           // A0,A1,B0,B1

// Issues the cp.async loads for one 128x64 A tile + 128x64 B tile.
// Per operand: 128 rows x 128 B = 1024 x 16B chunks, 4 per thread.
#define ISSUE_STAGE(aBaseU32, bBaseU32, Aptr, Bptr, stride, i0_, j0_, kofs)     \
    do {                                                                        \
        _Pragma("unroll")                                                       \
        for (int l = 0; l < 4; l++) {                                           \
            int id = tid + l * 256;                                             \
            int r  = id >> 3;                                                   \
            int c8 = (id & 7) * 8;                                              \
            uint32_t so = (uint32_t)(r * LDSMK + c8) * 2;                       \
            CP_ASYNC16((aBaseU32) + so,                                         \
                       &(Aptr)[(size_t)((i0_) + r) * (stride) + (kofs) + c8]);  \
            CP_ASYNC16((bBaseU32) + so,                                         \
                       &(Bptr)[(size_t)((j0_) + r) * (stride) + (kofs) + c8]);  \
        }                                                                       \
        CP_COMMIT();                                                            \
    } while (0)

// The 4-ks compute block on the current stage buffers (shared by both GEMMs)
#define COMPUTE_STAGE(aBase, bBase)                                             \
    _Pragma("unroll")                                                           \
    for (int ks = 0; ks < 4; ks++) {                                            \
        uint32_t af[2][4];                                                      \
        _Pragma("unroll")                                                       \
        for (int ti = 0; ti < 2; ti++) {                                        \
            int row = i0w + ti * 16 + (lane & 15);                              \
            uint32_t off = (uint32_t)(row * LDSMK + ks * 16 + ((lane >> 4) << 3)) * 2; \
            ldsm4((aBase) + off, af[ti]);                                       \
        }                                                                       \
        _Pragma("unroll")                                                       \
        for (int tp = 0; tp < 4; tp++) {                                        \
            uint32_t bf[4];                                                     \
            int row = j0w + tp * 16 + ((lane >> 4) << 3) + (lane & 7);          \
            uint32_t off = (uint32_t)(row * LDSMK + ks * 16 + (((lane >> 3) & 1) << 3)) * 2; \
            ldsm4((bBase) + off, bf);                                           \
            _Pragma("unroll")                                                   \
            for (int ti = 0; ti < 2; ti++) {                                    \
                mma16816(acc[ti][tp * 2], af[ti], bf[0], bf[1]);                \
                mma16816(acc[ti][tp * 2 + 1], af[ti], bf[2], bf[3]);            \
            }                                                                   \
        }                                                                       \
    }

// ---------------------------------------------------------------------------
// Kernel 3: feature GEMM on tensor cores (NT, bf16, fp32 accum), K = 1536
//   F[m,n] = dot(Xext[m,:], CextT[n,:]); epilogue stores gram features
//   x -> [hi|lo|hi],  y -> [hi|hi|lo].
// ---------------------------------------------------------------------------
__global__ __launch_bounds__(256, 2) void feat_mma() {
    extern __shared__ char smem[];

    const int tid  = threadIdx.x;
    const int wid  = tid >> 5;
    const int lane = tid & 31;

    const int isY = blockIdx.z;
    const __nv_bfloat16* Ag = isY ? g_ys : g_xs;
    const __nv_bfloat16* Bg = g_bsplit;
    __nv_bfloat16* __restrict__ dst = isY ? g_fy : g_fx;

    const int j0 = blockIdx.x * 128;
    const int i0 = blockIdx.y * 128;

    const int i0w = (wid & 3) * 32;
    const int j0w = (wid >> 2) * 64;

    const uint32_t aSm = smem_to_u32(smem);
    const uint32_t bSm = aSm + 2 * STAGE_B;

    float acc[2][8][4];
#pragma unroll
    for (int ti = 0; ti < 2; ti++)
#pragma unroll
        for (int tj = 0; tj < 8; tj++)
#pragma unroll
            for (int q = 0; q < 4; q++) acc[ti][tj][q] = 0.0f;

    ISSUE_STAGE(aSm, bSm, Ag, Bg, FEATX, i0, j0, 0);
    CP_WAIT0();
    __syncthreads();

    int buf = 0;
    for (int s = 0; s < FEATX / KC; s++) {
        const int kn = (s + 1) * KC;
        if (kn < FEATX) {
            const int nb = buf ^ 1;
            ISSUE_STAGE(aSm + nb * STAGE_B, bSm + nb * STAGE_B, Ag, Bg, FEATX,
                        i0, j0, kn);
        }

        COMPUTE_STAGE(aSm + buf * STAGE_B, bSm + buf * STAGE_B);

        CP_WAIT0();
        __syncthreads();
        buf ^= 1;
    }

    // Epilogue: split features into bf16 hi/lo, store 3 segments per row.
#pragma unroll
    for (int ti = 0; ti < 2; ti++) {
#pragma unroll
        for (int tj = 0; tj < 8; tj++) {
            int i = i0 + i0w + ti * 16 + (lane >> 2);
            int j = j0 + j0w + tj * 8 + (lane & 3) * 2;
#pragma unroll
            for (int half = 0; half < 2; half++) {
                int m = i + half * 8;
                uint32_t lv;
                uint32_t hv = split_pair(acc[ti][tj][half * 2],
                                         acc[ti][tj][half * 2 + 1], lv);
                size_t base = (size_t)m * FEAT3 + j;
                *(uint32_t*)&dst[base]            = hv;             // seg0: hi
                *(uint32_t*)&dst[base + FEAT]     = isY ? hv : lv;  // seg1
                *(uint32_t*)&dst[base + 2 * FEAT] = isY ? lv : hv;  // seg2
            }
        }
    }
}

// ---------------------------------------------------------------------------
// Kernel 4: batched Gram GEMM via mma.sync (bf16, fp32 accum), K = 768
// ---------------------------------------------------------------------------
__global__ __launch_bounds__(256, 2) void gram_mma(float* __restrict__ out) {
    extern __shared__ char smem[];

    const int tid  = threadIdx.x;
    const int wid  = tid >> 5;
    const int lane = tid & 31;

    const int b  = blockIdx.z;
    const int j0 = blockIdx.x * 128;
    const int i0 = blockIdx.y * 128;

    const __nv_bfloat16* Ag = g_fx + (size_t)b * NROWS * FEAT3;
    const __nv_bfloat16* Bg = g_fy + (size_t)b * NROWS * FEAT3;

    const int i0w = (wid & 3) * 32;
    const int j0w = (wid >> 2) * 64;

    const uint32_t aSm = smem_to_u32(smem);
    const uint32_t bSm = aSm + 2 * STAGE_B;

    float acc[2][8][4];
#pragma unroll
    for (int ti = 0; ti < 2; ti++)
#pragma unroll
        for (int tj = 0; tj < 8; tj++)
#pragma unroll
            for (int q = 0; q < 4; q++) acc[ti][tj][q] = 0.0f;

    ISSUE_STAGE(aSm, bSm, Ag, Bg, FEAT3, i0, j0, 0);
    CP_WAIT0();
    __syncthreads();

    int buf = 0;
    for (int s = 0; s < FEAT3 / KC; s++) {
        const int kn = (s + 1) * KC;
        if (kn < FEAT3) {
            const int nb = buf ^ 1;
            ISSUE_STAGE(aSm + nb * STAGE_B, bSm + nb * STAGE_B, Ag, Bg, FEAT3,
                        i0, j0, kn);
        }

        COMPUTE_STAGE(aSm + buf * STAGE_B, bSm + buf * STAGE_B);

        CP_WAIT0();
        __syncthreads();
        buf ^= 1;
    }

    const float scale = 1.0f / (float)RANK;
#pragma unroll
    for (int ti = 0; ti < 2; ti++) {
#pragma unroll
        for (int tj = 0; tj < 8; tj++) {
            int i = i0 + i0w + ti * 16 + (lane >> 2);
            int j = j0 + j0w + tj * 8 + (lane & 3) * 2;
            size_t base = ((size_t)b * NROWS + i) * NROWS + j;
            float2 v0 = make_float2(acc[ti][tj][0] * scale, acc[ti][tj][1] * scale);
            float2 v1 = make_float2(acc[ti][tj][2] * scale, acc[ti][tj][3] * scale);
            *(float2*)&out[base] = v0;
            *(float2*)&out[base + (size_t)8 * NROWS] = v1;
        }
    }
}

// ---------------------------------------------------------------------------
extern "C" void kernel_launch(void* const* d_in, const int* in_sizes, int n_in,
                              void* d_out, int out_size) {
    const float* x    = (const float*)d_in[0];
    const float* y    = (const float*)d_in[1];
    const float* filt = (const float*)d_in[2];
    float* out = (float*)d_out;

    // Opt-in to >48KB dynamic smem (attribute set, not an allocation)
    cudaFuncSetAttribute(feat_mma, cudaFuncAttributeMaxDynamicSharedMemorySize,
                         SMEM_TOTAL);
    cudaFuncSetAttribute(gram_mma, cudaFuncAttributeMaxDynamicSharedMemorySize,
                         SMEM_TOTAL);

    // 1) split transposed basis (256 x 1536 bf16)
    build_basis_t<<<FEAT * DIM / 256, 256>>>(filt);

    // 2) split x,y to bf16 [h|l|h] rows (K=1536)
    dim3 cgrid(MTOT * DIM / 4 / 256, 1, 2);
    convert_split<<<cgrid, 256>>>(x, y);

    // 3) feature GEMM on tensor cores -> gram features [hi|lo|hi]/[hi|hi|lo]
    dim3 fgrid(FEAT / 128, MTOT / 128, 2);
    feat_mma<<<fgrid, 256, SMEM_TOTAL>>>();

    // 4) batched Gram on tensor cores (K=768)
    dim3 ggrid(NROWS / 128, NROWS / 128, BATCH);
    gram_mma<<<ggrid, 256, SMEM_TOTAL>>>(out);
}